// round 6
// baseline (speedup 1.0000x reference)
#include <cuda_runtime.h>
#include <cuda_fp16.h>
#include <math.h>
#include <stdint.h>

#define FHH 32
#define FWW 88
#define NPIX 2816          // 32*88
#define NCAM 6
#define FCH 256            // conv channels
#define COUT 128           // BEV channels
#define ND 59              // depth bins
#define NVOX 16384         // 128*128 BEV cells

// ---------------- scratch (static device allocations) ----------------
__device__ __align__(16) __half g_imgh[NCAM * NPIX * FCH];   // NHWC fp16 input
__device__ __align__(16) __half g_h1h[NCAM * NPIX * FCH];    // NHWC fp16
__device__ __align__(16) __half g_h2h[NCAM * NPIX * FCH];    // NHWC fp16
__device__ __align__(16) float  g_feat[NCAM * NPIX * COUT];  // NHWC fp32
__device__ __align__(16) __half g_w1h[9 * FCH * FCH];        // [t][co][ci] fp16
__device__ __align__(16) __half g_w2h[9 * FCH * FCH];
__device__ __align__(16) __half g_w3h[COUT * FCH];           // [co][ci]
__device__ float g_scale1[FCH], g_scale2[FCH];
__device__ float g_beta1[FCH], g_beta2[FCH], g_beta3[COUT];
__device__ __align__(16) float g_bev[NVOX * COUT];           // [vox][c]

// ---------------- helpers ----------------
__device__ __forceinline__ uint32_t smem_u32(const void* p) {
    uint32_t a;
    asm("{ .reg .u64 t; cvta.to.shared.u64 t, %1; cvt.u32.u64 %0, t; }" : "=r"(a) : "l"(p));
    return a;
}
__device__ __forceinline__ void ldsm4(uint32_t* r, uint32_t addr) {
    asm volatile("ldmatrix.sync.aligned.m8n8.x4.shared.b16 {%0,%1,%2,%3}, [%4];"
                 : "=r"(r[0]), "=r"(r[1]), "=r"(r[2]), "=r"(r[3]) : "r"(addr));
}
__device__ __forceinline__ void mma_f16(float* d, const uint32_t* a, uint32_t b0, uint32_t b1) {
    asm volatile(
        "mma.sync.aligned.m16n8k16.row.col.f32.f16.f16.f32 "
        "{%0,%1,%2,%3}, {%4,%5,%6,%7}, {%8,%9}, {%0,%1,%2,%3};\n"
        : "+f"(d[0]), "+f"(d[1]), "+f"(d[2]), "+f"(d[3])
        : "r"(a[0]), "r"(a[1]), "r"(a[2]), "r"(a[3]), "r"(b0), "r"(b1));
}

// ---------------- setup: fold BN into scale/beta ----------------
__global__ void setup_kernel(const float* __restrict__ c1b,
                             const float* __restrict__ g1, const float* __restrict__ b1,
                             const float* __restrict__ m1, const float* __restrict__ v1,
                             const float* __restrict__ c2b,
                             const float* __restrict__ g2, const float* __restrict__ b2,
                             const float* __restrict__ m2, const float* __restrict__ v2,
                             const float* __restrict__ c3b)
{
    int i = threadIdx.x;
    if (i < FCH) {
        float s1 = g1[i] * rsqrtf(v1[i] + 1e-3f);
        g_scale1[i] = s1;
        g_beta1[i] = (c1b[i] - m1[i]) * s1 + b1[i];
        float s2 = g2[i] * rsqrtf(v2[i] + 1e-3f);
        g_scale2[i] = s2;
        g_beta2[i] = (c2b[i] - m2[i]) * s2 + b2[i];
    }
    if (i < COUT) g_beta3[i] = c3b[i];
}

// ---------------- weight transforms: (Co,Ci,3,3) -> [t][co][ci] fp16, scale folded ----------------
__global__ void wtrans3x3_kernel(const float* __restrict__ w,
                                 const float* __restrict__ scale,
                                 __half* __restrict__ out)
{
    int idx = blockIdx.x * blockDim.x + threadIdx.x;
    if (idx >= 9 * FCH * FCH) return;
    int t  = idx >> 16;
    int co = (idx >> 8) & 255;
    int ci = idx & 255;
    out[idx] = __float2half_rn(w[(co * FCH + ci) * 9 + t] * scale[co]);
}

__global__ void wtrans1x1_kernel(const float* __restrict__ w, __half* __restrict__ out)
{
    int idx = blockIdx.x * blockDim.x + threadIdx.x;   // [co][ci], same as source layout
    if (idx >= COUT * FCH) return;
    out[idx] = __float2half_rn(w[idx]);
}

// ---------------- NCHW fp32 -> NHWC fp16 ----------------
__global__ void nchw2nhwc_kernel(const float* __restrict__ in, __half* __restrict__ out)
{
    __shared__ float tile[32][33];
    int n  = blockIdx.z;
    int p0 = blockIdx.x * 32;
    int c0 = blockIdx.y * 32;
    int tx = threadIdx.x, ty = threadIdx.y;
    const float* src = in + (size_t)n * FCH * NPIX;
    __half* dst = out + (size_t)n * NPIX * FCH;
#pragma unroll
    for (int i = 0; i < 32; i += 8)
        tile[ty + i][tx] = src[(size_t)(c0 + ty + i) * NPIX + p0 + tx];
    __syncthreads();
#pragma unroll
    for (int i = 0; i < 32; i += 8)
        dst[(size_t)(p0 + ty + i) * FCH + c0 + tx] = __float2half_rn(tile[tx][ty + i]);
}

// ---------------- NHWC fp16 implicit-GEMM conv: M=pix, N=co, mma.m16n8k16 ----------------
// Tile: 128 pix x 128 co, BK=32, 256 threads (8 warps: 2 pix-groups x 4 co-groups).
// A smem [128 pix][32 ch], B smem [128 co][32 ch]; rows padded to 40 halves (80B = 5 segs).
template <int TAPS, bool RELU, typename OutT>
__global__ void __launch_bounds__(256, 2)
conv_fp16_kernel(const __half* __restrict__ in_all, const __half* __restrict__ wtt,
                 const float* __restrict__ beta, OutT* __restrict__ out_all,
                 int Cin, int Cout)
{
    __shared__ __align__(16) __half As[128 * 40];   // [pix][k]
    __shared__ __align__(16) __half Bs[128 * 40];   // [co][k]
    const uint32_t abase = smem_u32(As);
    const uint32_t bbase = smem_u32(Bs);

    const int n   = blockIdx.z;
    const __half* in = in_all + (size_t)n * NPIX * Cin;
    OutT*        out = out_all + (size_t)n * NPIX * Cout;
    const int p0  = blockIdx.x * 128;
    const int co0 = blockIdx.y * 128;
    const int tid = threadIdx.x;
    const int lane = tid & 31;
    const int wid  = tid >> 5;
    const int wm0 = (wid & 1) * 64;    // pixel offset of warp
    const int wn0 = (wid >> 1) * 32;   // co offset of warp

    // loader geometry: 2 threads per row, 32B halves
    const int lr = tid >> 1;           // row 0..127
    const int lh = tid & 1;            // half 0/1 (16 halves each)
    const int p  = p0 + lr;
    const int hh = p / FWW;
    const int ww = p % FWW;

    const int KIT = Cin / 32;
    const int S = TAPS * KIT;

    float acc[4][4][4];
#pragma unroll
    for (int mi = 0; mi < 4; mi++)
#pragma unroll
        for (int ni = 0; ni < 4; ni++)
#pragma unroll
            for (int r = 0; r < 4; r++) acc[mi][ni][r] = 0.f;

    // ldmatrix lane addressing (non-transposed)
    const int arow = lane & 15;                  // A: mats 0,1 rows 0-15 @k0; mats 2,3 @k+16B
    const int akoff = (lane >> 4) * 16;
    const int brow = (lane & 7) + ((lane >> 4) ? 8 : 0);   // B: co row
    const int bkoff = ((lane >> 3) & 1) * 16;

    for (int s = 0; s < S; ++s) {
        const int t  = s / KIT;
        const int k0 = (s % KIT) * 32;

        // ---- stage A: activations [128 pix][32 ch], tap-shifted, vectorized ----
        {
            bool valid;
            int ps;
            if (TAPS == 1) { valid = true; ps = p; }
            else {
                int dy = t / 3 - 1, dx = t % 3 - 1;
                int h2 = hh + dy, w2 = ww + dx;
                valid = (h2 >= 0) && (h2 < FHH) && (w2 >= 0) && (w2 < FWW);
                ps = h2 * FWW + w2;
            }
            uint32_t dst = abase + (uint32_t)(lr * 80 + lh * 32);
            if (valid) {
                const uint4* src = (const uint4*)(in + (size_t)ps * Cin + k0 + lh * 16);
                uint4 v0 = src[0], v1 = src[1];
                asm volatile("st.shared.v4.b32 [%0], {%1,%2,%3,%4};" :: "r"(dst),      "r"(v0.x), "r"(v0.y), "r"(v0.z), "r"(v0.w) : "memory");
                asm volatile("st.shared.v4.b32 [%0], {%1,%2,%3,%4};" :: "r"(dst + 16), "r"(v1.x), "r"(v1.y), "r"(v1.z), "r"(v1.w) : "memory");
            } else {
                asm volatile("st.shared.v4.b32 [%0], {%1,%1,%1,%1};" :: "r"(dst),      "r"(0u) : "memory");
                asm volatile("st.shared.v4.b32 [%0], {%1,%1,%1,%1};" :: "r"(dst + 16), "r"(0u) : "memory");
            }
        }
        // ---- stage B: weights [128 co][32 ci], vectorized ----
        {
            const uint4* src = (const uint4*)(wtt + ((size_t)t * Cout + co0 + lr) * Cin + k0 + lh * 16);
            uint4 v0 = src[0], v1 = src[1];
            uint32_t dst = bbase + (uint32_t)(lr * 80 + lh * 32);
            asm volatile("st.shared.v4.b32 [%0], {%1,%2,%3,%4};" :: "r"(dst),      "r"(v0.x), "r"(v0.y), "r"(v0.z), "r"(v0.w) : "memory");
            asm volatile("st.shared.v4.b32 [%0], {%1,%2,%3,%4};" :: "r"(dst + 16), "r"(v1.x), "r"(v1.y), "r"(v1.z), "r"(v1.w) : "memory");
        }
        __syncthreads();

        // ---- compute: 2 k16 steps ----
#pragma unroll
        for (int ks = 0; ks < 2; ks++) {
            const int kb = ks * 32;     // bytes into the 64B k-span
            uint32_t a[4][4];
#pragma unroll
            for (int mi = 0; mi < 4; mi++)
                ldsm4(a[mi], abase + (uint32_t)((wm0 + mi * 16 + arow) * 80 + kb + akoff));
#pragma unroll
            for (int np = 0; np < 2; np++) {
                uint32_t b[4];
                ldsm4(b, bbase + (uint32_t)((wn0 + np * 16 + brow) * 80 + kb + bkoff));
#pragma unroll
                for (int mi = 0; mi < 4; mi++) {
                    mma_f16(acc[mi][np * 2],     a[mi], b[0], b[1]);
                    mma_f16(acc[mi][np * 2 + 1], a[mi], b[2], b[3]);
                }
            }
        }
        __syncthreads();
    }

    // ---- epilogue: +beta, relu, NHWC stores ----
#pragma unroll
    for (int ni = 0; ni < 4; ni++) {
        int co = co0 + wn0 + ni * 8 + (lane & 3) * 2;
        float2 be = *(const float2*)(beta + co);
#pragma unroll
        for (int mi = 0; mi < 4; mi++) {
            int pix0 = p0 + wm0 + mi * 16 + (lane >> 2);
            int pix1 = pix0 + 8;
            float v0 = acc[mi][ni][0] + be.x;
            float v1 = acc[mi][ni][1] + be.y;
            float v2 = acc[mi][ni][2] + be.x;
            float v3 = acc[mi][ni][3] + be.y;
            if (RELU) {
                v0 = fmaxf(v0, 0.f); v1 = fmaxf(v1, 0.f);
                v2 = fmaxf(v2, 0.f); v3 = fmaxf(v3, 0.f);
            }
            if (sizeof(OutT) == 2) {
                __half2 h0 = __floats2half2_rn(v0, v1);
                __half2 h1 = __floats2half2_rn(v2, v3);
                *(uint32_t*)((__half*)out + (size_t)pix0 * Cout + co) = *(uint32_t*)&h0;
                *(uint32_t*)((__half*)out + (size_t)pix1 * Cout + co) = *(uint32_t*)&h1;
            } else {
                *(float2*)((float*)out + (size_t)pix0 * Cout + co) = make_float2(v0, v1);
                *(float2*)((float*)out + (size_t)pix1 * Cout + co) = make_float2(v2, v3);
            }
        }
    }
}

// ---------------- zero the scratch BEV ----------------
__global__ void zero_bev_kernel()
{
    int idx = blockIdx.x * blockDim.x + threadIdx.x;
    float4 z = make_float4(0.f, 0.f, 0.f, 0.f);
    for (int i = idx; i < NVOX * COUT / 4; i += gridDim.x * blockDim.x)
        ((float4*)g_bev)[i] = z;
}

// ---------------- fused depth-softmax + lift + splat (NHWC feat) ----------------
__global__ void __launch_bounds__(128)
splat_kernel(const float* __restrict__ rel, const int* __restrict__ vox,
             const float* __restrict__ log_scale, const float* __restrict__ shift,
             const float* __restrict__ log_sigma, const float* __restrict__ feat)
{
    const int pb = blockIdx.x;
    const int n = pb / NPIX;
    const int p = pb % NPIX;
    const int tid = threadIdx.x;

    __shared__ float sw[ND];
    __shared__ int   sv[ND];
    __shared__ __align__(16) float sf[COUT];
    __shared__ float s_mx, s_inv;

    const float metric = fminf(fmaxf(expf(log_scale[0]) * rel[n * NPIX + p] + shift[0], 0.5f), 150.f);
    const float sigma  = fminf(fmaxf(expf(log_sigma[0]), 0.1f), 20.f);

    if (tid < ND) {
        sw[tid] = -fabsf(metric - (float)(tid + 1)) / sigma;
        sv[tid] = vox[(size_t)(n * ND + tid) * NPIX + p];
    }
    sf[tid] = feat[((size_t)(n * NPIX + p)) * COUT + tid];
    __syncthreads();

    if (tid == 0) {
        float mx = -1e30f;
        for (int d = 0; d < ND; d++) mx = fmaxf(mx, sw[d]);
        float s = 0.f;
        for (int d = 0; d < ND; d++) s += expf(sw[d] - mx);
        s_mx = mx;
        s_inv = 1.f / s;
    }
    __syncthreads();
    if (tid < ND) sw[tid] = expf(sw[tid] - s_mx) * s_inv;
    __syncthreads();

    const int lane = tid & 31;
    const int wid  = tid >> 5;
    float4 f = *(const float4*)&sf[lane * 4];
    for (int d = wid; d < ND; d += 4) {
        float wg = sw[d];
        float4 v = make_float4(wg * f.x, wg * f.y, wg * f.z, wg * f.w);
        atomicAdd((float4*)&g_bev[(size_t)sv[d] * COUT + lane * 4], v);
    }
}

// ---------------- transpose [vox][c] -> output (C, X*Y) ----------------
__global__ void transpose_kernel(float* __restrict__ out)
{
    __shared__ float tile[32][33];
    int v0 = blockIdx.x * 32;
    int c0 = blockIdx.y * 32;
    int tx = threadIdx.x;
    int ty = threadIdx.y;
#pragma unroll
    for (int i = 0; i < 32; i += 8)
        tile[ty + i][tx] = g_bev[(size_t)(v0 + ty + i) * COUT + c0 + tx];
    __syncthreads();
#pragma unroll
    for (int i = 0; i < 32; i += 8)
        out[(size_t)(c0 + ty + i) * NVOX + v0 + tx] = tile[tx][ty + i];
}

// ---------------- launch ----------------
extern "C" void kernel_launch(void* const* d_in, const int* in_sizes, int n_in,
                              void* d_out, int out_size)
{
    const float* rel       = (const float*)d_in[0];
    const float* img       = (const float*)d_in[1];
    const int*   vox       = (const int*)d_in[2];
    const float* log_scale = (const float*)d_in[3];
    const float* shift     = (const float*)d_in[4];
    const float* log_sigma = (const float*)d_in[5];
    const float* w1  = (const float*)d_in[6];
    const float* c1b = (const float*)d_in[7];
    const float* g1  = (const float*)d_in[8];
    const float* b1  = (const float*)d_in[9];
    const float* m1  = (const float*)d_in[10];
    const float* v1  = (const float*)d_in[11];
    const float* w2  = (const float*)d_in[12];
    const float* c2b = (const float*)d_in[13];
    const float* g2  = (const float*)d_in[14];
    const float* b2  = (const float*)d_in[15];
    const float* m2  = (const float*)d_in[16];
    const float* v2  = (const float*)d_in[17];
    const float* w3  = (const float*)d_in[18];
    const float* c3b = (const float*)d_in[19];
    float* out = (float*)d_out;

    __half *imghp, *h1p, *h2p, *w1hp, *w2hp, *w3hp;
    float *featp, *sc1p, *sc2p, *be1p, *be2p, *be3p;
    cudaGetSymbolAddress((void**)&imghp, g_imgh);
    cudaGetSymbolAddress((void**)&h1p,   g_h1h);
    cudaGetSymbolAddress((void**)&h2p,   g_h2h);
    cudaGetSymbolAddress((void**)&featp, g_feat);
    cudaGetSymbolAddress((void**)&w1hp,  g_w1h);
    cudaGetSymbolAddress((void**)&w2hp,  g_w2h);
    cudaGetSymbolAddress((void**)&w3hp,  g_w3h);
    cudaGetSymbolAddress((void**)&sc1p,  g_scale1);
    cudaGetSymbolAddress((void**)&sc2p,  g_scale2);
    cudaGetSymbolAddress((void**)&be1p,  g_beta1);
    cudaGetSymbolAddress((void**)&be2p,  g_beta2);
    cudaGetSymbolAddress((void**)&be3p,  g_beta3);

    dim3 cgrid(NPIX / 128, FCH / 128, NCAM);     // (22, 2, 6)
    dim3 cgrid3(NPIX / 128, 1, NCAM);            // (22, 1, 6)

    // order chosen so conv1 is at launch index 3 (the slot ncu -s 5 actually captures)
    setup_kernel<<<1, 256>>>(c1b, g1, b1, m1, v1, c2b, g2, b2, m2, v2, c3b);            // 0
    wtrans3x3_kernel<<<(9 * FCH * FCH + 255) / 256, 256>>>(w1, sc1p, w1hp);             // 1
    nchw2nhwc_kernel<<<dim3(NPIX / 32, FCH / 32, NCAM), dim3(32, 8)>>>(img, imghp);     // 2
    conv_fp16_kernel<9, true, __half><<<cgrid, 256>>>(imghp, w1hp, be1p, h1p, FCH, FCH);   // 3
    wtrans3x3_kernel<<<(9 * FCH * FCH + 255) / 256, 256>>>(w2, sc2p, w2hp);             // 4
    conv_fp16_kernel<9, true, __half><<<cgrid, 256>>>(h1p, w2hp, be2p, h2p, FCH, FCH);     // 5
    wtrans1x1_kernel<<<(COUT * FCH + 255) / 256, 256>>>(w3, w3hp);                      // 6
    conv_fp16_kernel<1, false, float><<<cgrid3, 256>>>(h2p, w3hp, be3p, featp, FCH, COUT); // 7
    zero_bev_kernel<<<2048, 256>>>();                                                   // 8
    splat_kernel<<<NCAM * NPIX, 128>>>(rel, vox, log_scale, shift, log_sigma, featp);   // 9
    transpose_kernel<<<dim3(NVOX / 32, COUT / 32), dim3(32, 8)>>>(out);                 // 10
}